// round 2
// baseline (speedup 1.0000x reference)
#include <cuda_runtime.h>
#include <cstdint>

#define OUT_F 28672
#define IN_F  8192
#define ROW_INTS (IN_F / 2)      // 4096 int32 elements per row (one byte-value each)
#define ROW_UINT4 (ROW_INTS / 4) // 1024 uint4 per row
#define RPB 32                   // rows per block
#define NW  8                    // warps per block

// qweight arrives as int32 (harness widens uint8 -> int32): each element is one
// byte value 0..255 holding two 4-bit codes (lo nibble = even col, hi = odd col).
// Warp w owns ints [512w, 512w+512) of every row. Pass k (0..3), lane l loads the
// uint4 at index 128w + 32k + l  ->  ints 512w+128k+4l..+3  ->  columns
// 1024w + 256k + 8l .. +7. x for those columns is preloaded into registers.

__global__ __launch_bounds__(256)
void q3_matvec_kernel(const float* __restrict__ x,
                      const int* __restrict__ qw,
                      const float* __restrict__ kv,
                      const float* __restrict__ bias,
                      float* __restrict__ y)
{
    __shared__ float s_lut[RPB * 16];   // 32 rows x 16-entry fp32 LUT (bank-conflict-free)
    __shared__ float s_part[RPB * NW];  // per-(row,warp) partials

    const int t = threadIdx.x;
    const int w = t >> 5;
    const int l = t & 31;
    const int row0 = blockIdx.x * RPB;

    // Stage 32 row-LUTs: 512 floats = 256 float2, one per thread.
    {
        const float2* kvp = reinterpret_cast<const float2*>(kv + (size_t)row0 * 16);
        reinterpret_cast<float2*>(s_lut)[t] = kvp[t];
    }

    // x slice: 4 chunks of 8 consecutive floats matching the qweight passes.
    float xr[32];
    #pragma unroll
    for (int k = 0; k < 4; k++) {
        const float4* xp = reinterpret_cast<const float4*>(x + (w << 10) + (k << 8) + (l << 3));
        float4 v0 = xp[0], v1 = xp[1];
        xr[8*k+0] = v0.x; xr[8*k+1] = v0.y; xr[8*k+2] = v0.z; xr[8*k+3] = v0.w;
        xr[8*k+4] = v1.x; xr[8*k+5] = v1.y; xr[8*k+6] = v1.z; xr[8*k+7] = v1.w;
    }
    __syncthreads();

    const uint4* qbase = reinterpret_cast<const uint4*>(qw)
                       + (size_t)row0 * ROW_UINT4 + (w << 7) + l;

    // Prefetch row 0 (4 passes x 16 B per lane).
    uint4 q0 = qbase[0], q1 = qbase[32], q2 = qbase[64], q3 = qbase[96];

    for (int r = 0; r < RPB; r++) {
        // Prefetch next row while computing on the current one.
        uint4 n0, n1, n2, n3;
        if (r + 1 < RPB) {
            const uint4* qn = qbase + (size_t)(r + 1) * ROW_UINT4;
            n0 = qn[0]; n1 = qn[32]; n2 = qn[64]; n3 = qn[96];
        } else {
            n0 = n1 = n2 = n3 = make_uint4(0u, 0u, 0u, 0u);
        }

        const float* lut = s_lut + r * 16;
        float a0 = 0.f, a1 = 0.f, a2 = 0.f, a3 = 0.f;

        // One uint4 = 4 int32 byte-values = 8 columns.
        #define DO_VEC(Q, KB)                                              \
        {                                                                  \
            a0 = fmaf(lut[(Q).x & 15u],        xr[(KB)+0], a0);            \
            a1 = fmaf(lut[((Q).x >> 4) & 15u], xr[(KB)+1], a1);            \
            a2 = fmaf(lut[(Q).y & 15u],        xr[(KB)+2], a2);            \
            a3 = fmaf(lut[((Q).y >> 4) & 15u], xr[(KB)+3], a3);            \
            a0 = fmaf(lut[(Q).z & 15u],        xr[(KB)+4], a0);            \
            a1 = fmaf(lut[((Q).z >> 4) & 15u], xr[(KB)+5], a1);            \
            a2 = fmaf(lut[(Q).w & 15u],        xr[(KB)+6], a2);            \
            a3 = fmaf(lut[((Q).w >> 4) & 15u], xr[(KB)+7], a3);            \
        }

        DO_VEC(q0, 0)
        DO_VEC(q1, 8)
        DO_VEC(q2, 16)
        DO_VEC(q3, 24)
        #undef DO_VEC

        q0 = n0; q1 = n1; q2 = n2; q3 = n3;

        float acc = (a0 + a1) + (a2 + a3);
        #pragma unroll
        for (int s = 16; s > 0; s >>= 1)
            acc += __shfl_xor_sync(0xffffffffu, acc, s);
        if (l == 0) s_part[r * NW + w] = acc;
    }
    __syncthreads();

    // Cross-warp reduce + bias + store: 32 rows handled by threads 0..31.
    if (t < RPB) {
        float s = 0.f;
        #pragma unroll
        for (int i = 0; i < NW; i++) s += s_part[t * NW + i];
        y[row0 + t] = s + bias[row0 + t];
    }
}

extern "C" void kernel_launch(void* const* d_in, const int* in_sizes, int n_in,
                              void* d_out, int out_size)
{
    const float* x    = (const float*)d_in[0];
    const int*   qw   = (const int*)d_in[1];
    const float* kv   = (const float*)d_in[2];
    const float* bias = (const float*)d_in[3];
    float*       y    = (float*)d_out;

    dim3 grid(OUT_F / RPB);   // 896 blocks
    dim3 block(256);
    q3_matvec_kernel<<<grid, block>>>(x, qw, kv, bias, y);
}